// round 15
// baseline (speedup 1.0000x reference)
#include <cuda_runtime.h>
#include <math.h>

#define NMAX 100000
#define EMAX 1600000
#define C_IN 64
#define C_OUT 128
#define GRPB 32                      // gemm rows per block
#define NB_SCAN ((NMAX + 1023) / 1024)

// Scratch (device globals — no allocations allowed)
__device__ float g_y[(size_t)NMAX * C_IN];
__device__ float g_x0[(size_t)NMAX * C_IN];
__device__ float g_x1[(size_t)NMAX * C_IN];
__device__ float g_dinv[NMAX];
__device__ int   g_cnt[NMAX];        // must be 0 at entry of every call (invariant)
__device__ int   g_fillctr[NMAX];
__device__ int   g_rowstart[NMAX + 1];
__device__ int2  g_edge[EMAX];       // {srcid, coef bits}
__device__ int   g_blocksum[NB_SCAN];
__device__ int   g_flag[NB_SCAN];    // must be 0 at entry (reset by fill_kernel)
__device__ int   g_bar_arrive;
__device__ int   g_bar_depart;

__device__ __forceinline__ int clampi(int v, int lo, int hi) {
    return v < lo ? lo : (v > hi ? hi : v);
}

// ---- f32x2 packed math helpers ----
__device__ __forceinline__ unsigned long long pack2(float lo, float hi) {
    unsigned long long r;
    asm("mov.b64 %0, {%1, %2};" : "=l"(r) : "f"(lo), "f"(hi));
    return r;
}
__device__ __forceinline__ void unpack2(unsigned long long v, float& lo, float& hi) {
    asm("mov.b64 {%0, %1}, %2;" : "=f"(lo), "=f"(hi) : "l"(v));
}
#define FMA_F32X2(d, a, b, c) \
    asm("fma.rn.f32x2 %0, %1, %2, %3;" : "=l"(d) : "l"(a), "l"(b), "l"(c))

// self-resetting grid barrier (all nb blocks resident)
__device__ __forceinline__ void grid_barrier(int nb) {
    __syncthreads();
    if (threadIdx.x == 0) {
        __threadfence();
        atomicAdd(&g_bar_arrive, 1);
        while (atomicAdd(&g_bar_arrive, 0) < nb) { }
        int d = atomicAdd(&g_bar_depart, 1);
        if (d == nb - 1) {
            g_bar_arrive = 0;
            g_bar_depart = 0;
            __threadfence();
        }
    }
    __syncthreads();
}

// ---------------- launch 1: count + scan (fused, persistent) ---------------
__global__ void __launch_bounds__(1024) csr_scan_kernel(
        const int* __restrict__ dst, int e, int n, int nb) {
    for (int i = blockIdx.x * 1024 + threadIdx.x; i < e; i += nb * 1024)
        atomicAdd(&g_cnt[clampi(dst[i], 0, n - 1)], 1);

    grid_barrier(nb);

    __shared__ int sm[1024];
    __shared__ int prefix_sm;
    const int b = blockIdx.x;
    const int i = b * 1024 + threadIdx.x;

    int v = (i < n) ? g_cnt[i] : 0;
    sm[threadIdx.x] = v;
    __syncthreads();
    #pragma unroll
    for (int off = 1; off < 1024; off <<= 1) {
        int t = (threadIdx.x >= off) ? sm[threadIdx.x - off] : 0;
        __syncthreads();
        sm[threadIdx.x] += t;
        __syncthreads();
    }
    const int total = sm[1023];

    if (threadIdx.x == 0) {
        prefix_sm = 0;
        g_blocksum[b] = total;
        __threadfence();
        atomicExch(&g_flag[b], 1);
    }
    __syncthreads();

    int local = 0;
    for (int p = threadIdx.x; p < b; p += 1024) {
        while (atomicAdd(&g_flag[p], 0) == 0) { }
        local += g_blocksum[p];
    }
    if (local) atomicAdd(&prefix_sm, local);
    __syncthreads();
    const int prefix = prefix_sm;

    if (i < n) {
        int rs = prefix + sm[threadIdx.x] - v;
        g_rowstart[i] = rs;
        g_fillctr[i]  = rs;
        g_dinv[i]     = rsqrtf((float)v + 1.0f);
        g_cnt[i]      = 0;
    }
    if (b == nb - 1 && threadIdx.x == 0) g_rowstart[n] = prefix + total;
}

// ---------------- launch 2: fill edges (and reset lookback flags) ---------
__global__ void fill_kernel(const int* __restrict__ src,
                            const int* __restrict__ dst, int e, int n, int nb) {
    int i = blockIdx.x * blockDim.x + threadIdx.x;
    if (i < nb) g_flag[i] = 0;
    if (i >= e) return;
    int s = clampi(src[i], 0, n - 1);
    int d = clampi(dst[i], 0, n - 1);
    int pos = atomicAdd(&g_fillctr[d], 1);
    g_edge[pos] = make_int2(s, __float_as_int(g_dinv[s] * g_dinv[d]));
}

// ---------------- aggregate in x-space (64 ch) ----------------
__global__ void __launch_bounds__(256)
agg_kernel(const float* __restrict__ xin, int n) {
    int node = (blockIdx.x * blockDim.x + threadIdx.x) >> 5;
    if (node >= n) return;
    int lane = threadIdx.x & 31;
    int half = lane >> 4;
    int hl = lane & 15;

    const float4* x4 = reinterpret_cast<const float4*>(xin);
    float4 acc = make_float4(0.f, 0.f, 0.f, 0.f);

    int e0 = g_rowstart[node];
    int e1 = g_rowstart[node + 1];
    #pragma unroll 4
    for (int t = e0 + half; t < e1; t += 2) {
        int2 ed = __ldg(&g_edge[t]);
        float c = __int_as_float(ed.y);
        float4 v = __ldg(&x4[(size_t)ed.x * 16 + hl]);
        acc.x = fmaf(v.x, c, acc.x);
        acc.y = fmaf(v.y, c, acc.y);
        acc.z = fmaf(v.z, c, acc.z);
        acc.w = fmaf(v.w, c, acc.w);
    }
    __syncwarp();
    acc.x += __shfl_xor_sync(0xffffffffu, acc.x, 16);
    acc.y += __shfl_xor_sync(0xffffffffu, acc.y, 16);
    acc.z += __shfl_xor_sync(0xffffffffu, acc.z, 16);
    acc.w += __shfl_xor_sync(0xffffffffu, acc.w, 16);

    if (half == 0) {
        float dv = g_dinv[node], s2 = dv * dv;
        float4 xs = __ldg(&x4[(size_t)node * 16 + hl]);
        acc.x = fmaf(xs.x, s2, acc.x);
        acc.y = fmaf(xs.y, s2, acc.y);
        acc.z = fmaf(xs.z, s2, acc.z);
        acc.w = fmaf(xs.w, s2, acc.w);
        reinterpret_cast<float4*>(g_y)[(size_t)node * 16 + hl] = acc;
    }
}

// ---------------- k-split packed GEMM + bias + GLU + residual -------------
// 256 threads = 8 warps = 4 row-groups x 2 col-groups.
// Warp: 8 rows x 32 GLU col-pairs. Lane owns cols cA = 32*cg + L and cG = cA+64.
// 16 f32x2 accumulators/thread (k-split over even/odd k).
__global__ void __launch_bounds__(256, 3)
gemm_glu_kernel(const float* __restrict__ xin, float* __restrict__ xout,
                const float* __restrict__ W, const float* __restrict__ b,
                int n) {
    __shared__ __align__(16) unsigned long long wsp2[C_IN / 2][C_OUT]; // 32 KB
    __shared__ __align__(16) unsigned long long ysp2[GRPB][C_IN / 2];  // 8 KB

    const int t = threadIdx.x;
    const int warp = t >> 5;
    const int lane = t & 31;
    const int rg = warp >> 1;            // 0..3
    const int cg = warp & 1;             // 0..1
    const int row0 = blockIdx.x * GRPB;
    const int rbase = 8 * rg;
    const int cA = 32 * cg + lane;       // a-col
    const int cG = cA + 64;              // g-col

    // stage W k-pair packed: wsp2[k2][c] = (W[2k2][c], W[2k2+1][c]); coalesced
    #pragma unroll
    for (int idx = t; idx < (C_IN / 2) * C_OUT; idx += 256) {
        int k2 = idx >> 7, c = idx & 127;
        wsp2[k2][c] = pack2(W[(2 * k2) * C_OUT + c], W[(2 * k2 + 1) * C_OUT + c]);
    }
    // stage y rows verbatim (ulonglong2 = 4 floats)
    {
        const ulonglong2* ysrc = reinterpret_cast<const ulonglong2*>(g_y);
        ulonglong2* ydst = reinterpret_cast<ulonglong2*>(ysp2);
        #pragma unroll
        for (int idx = t; idx < GRPB * (C_IN / 4); idx += 256) {
            int row = row0 + (idx >> 4);
            ydst[idx] = (row < n) ? ysrc[(size_t)row0 * 16 + idx]
                                  : make_ulonglong2(0ull, 0ull);
        }
    }
    __syncthreads();

    unsigned long long aA[8], aG[8];
    #pragma unroll
    for (int r = 0; r < 8; r++) { aA[r] = 0ull; aG[r] = 0ull; }

    #pragma unroll 4
    for (int k2 = 0; k2 < C_IN / 2; k2 += 2) {
        // weights for 2 k2's x 2 cols: 4x LDS.64
        unsigned long long wa0 = wsp2[k2][cA];
        unsigned long long wa1 = wsp2[k2 + 1][cA];
        unsigned long long wg0 = wsp2[k2][cG];
        unsigned long long wg1 = wsp2[k2 + 1][cG];
        #pragma unroll
        for (int r = 0; r < 8; r++) {
            // y for row, 4 k's: 1x LDS.128 broadcast
            ulonglong2 yv = *reinterpret_cast<const ulonglong2*>(&ysp2[rbase + r][k2]);
            FMA_F32X2(aA[r], yv.x, wa0, aA[r]);
            FMA_F32X2(aA[r], yv.y, wa1, aA[r]);
            FMA_F32X2(aG[r], yv.x, wg0, aG[r]);
            FMA_F32X2(aG[r], yv.y, wg1, aG[r]);
        }
    }

    const float bA = __ldg(&b[cA]);
    const float bG = __ldg(&b[cG]);

    // epilogue: k-split reduce + GLU + residual; 32 consecutive floats/warp/row
    #pragma unroll
    for (int r = 0; r < 8; r++) {
        int row = row0 + rbase + r;
        if (row >= n) break;
        float lo, hi;
        unpack2(aA[r], lo, hi); float av = lo + hi + bA;
        unpack2(aG[r], lo, hi); float gv = lo + hi + bG;
        float res = xin[(size_t)row * C_IN + cA];
        xout[(size_t)row * C_IN + cA] =
            fmaf(av, 1.0f / (1.0f + expf(-gv)), res);
    }
}

extern "C" void kernel_launch(void* const* d_in, const int* in_sizes, int n_in,
                              void* d_out, int out_size) {
    // Identify inputs by SIZE:
    //   x: == out_size (6.4M f32); edge_index: largest rest (3.2M i32);
    //   Ws: next (24576 f32); bs: smallest (384 f32)
    const float* x = nullptr; const float* Ws = nullptr; const float* bs = nullptr;
    const int* ei = nullptr;
    int ei_elems = 0, Ws_elems = 0;
    int used[16] = {0};
    for (int i = 0; i < n_in; i++)
        if (!x && in_sizes[i] == out_size) { x = (const float*)d_in[i]; used[i] = 1; break; }
    {
        int best = -1, bsz = -1;
        for (int i = 0; i < n_in; i++)
            if (!used[i] && in_sizes[i] > bsz) { bsz = in_sizes[i]; best = i; }
        ei = (const int*)d_in[best]; ei_elems = bsz; used[best] = 1;
    }
    {
        int best = -1, bsz = -1;
        for (int i = 0; i < n_in; i++)
            if (!used[i] && in_sizes[i] > bsz) { bsz = in_sizes[i]; best = i; }
        Ws = (const float*)d_in[best]; Ws_elems = bsz; used[best] = 1;
    }
    for (int i = 0; i < n_in; i++)
        if (!used[i]) { bs = (const float*)d_in[i]; used[i] = 1; break; }

    const int n = out_size / C_IN;
    const int e = ei_elems / 2;
    const int L = Ws_elems / (C_IN * C_OUT);
    const int* src = ei;
    const int* dst = ei + e;
    const int nb = (n + 1023) / 1024;   // 98 blocks, all resident

    float *x0, *x1;
    cudaGetSymbolAddress((void**)&x0, g_x0);
    cudaGetSymbolAddress((void**)&x1, g_x1);

    // ---- CSR build: 2 launches ----
    csr_scan_kernel<<<nb, 1024>>>(dst, e, n, nb);
    fill_kernel<<<(e + 255) / 256, 256>>>(src, dst, e, n, nb);

    // ---- layers (gemm of layer 0 is launch 4 -> profiled) ----
    const float* xin = x;
    for (int l = 0; l < L; l++) {
        float* xout = (l == L - 1) ? (float*)d_out : ((l & 1) ? x1 : x0);
        agg_kernel<<<(n * 32 + 255) / 256, 256>>>(xin, n);
        gemm_glu_kernel<<<(n + GRPB - 1) / GRPB, 256>>>(
            xin, xout, Ws + (size_t)l * C_IN * C_OUT, bs + (size_t)l * C_OUT, n);
        xin = xout;
    }
}

// round 16
// speedup vs baseline: 1.2586x; 1.2586x over previous
#include <cuda_runtime.h>
#include <math.h>

#define NMAX 100000
#define EMAX 1600000
#define C_IN 64
#define C_OUT 128
#define GRPB 32                      // gemm rows per block
#define NB_SCAN ((NMAX + 1023) / 1024)

// Scratch (device globals — no allocations allowed)
__device__ float g_y[(size_t)NMAX * C_IN];
__device__ float g_x0[(size_t)NMAX * C_IN];
__device__ float g_x1[(size_t)NMAX * C_IN];
__device__ float g_dinv[NMAX];
__device__ int   g_cnt[NMAX];        // must be 0 at entry of every call (invariant)
__device__ int   g_fillctr[NMAX];
__device__ int   g_rowstart[NMAX + 1];
__device__ int2  g_edge[EMAX];       // {srcid, coef bits}
__device__ int   g_blocksum[NB_SCAN];
__device__ int   g_flag[NB_SCAN];    // must be 0 at entry (reset by fill_kernel)
__device__ int   g_bar_arrive;
__device__ int   g_bar_depart;

__device__ __forceinline__ int clampi(int v, int lo, int hi) {
    return v < lo ? lo : (v > hi ? hi : v);
}

__device__ __forceinline__ unsigned int tf32_rna(float f) {
    unsigned int r;
    asm("cvt.rna.tf32.f32 %0, %1;" : "=r"(r) : "f"(f));
    return r;
}

__device__ __forceinline__ void mma_tf32(
    float& d0, float& d1, float& d2, float& d3,
    unsigned int a0, unsigned int a1, unsigned int a2, unsigned int a3,
    unsigned int b0, unsigned int b1) {
    asm("mma.sync.aligned.m16n8k8.row.col.f32.tf32.tf32.f32 "
        "{%0,%1,%2,%3}, {%4,%5,%6,%7}, {%8,%9}, {%0,%1,%2,%3};"
        : "+f"(d0), "+f"(d1), "+f"(d2), "+f"(d3)
        : "r"(a0), "r"(a1), "r"(a2), "r"(a3), "r"(b0), "r"(b1));
}

// self-resetting grid barrier (all nb blocks resident)
__device__ __forceinline__ void grid_barrier(int nb) {
    __syncthreads();
    if (threadIdx.x == 0) {
        __threadfence();
        atomicAdd(&g_bar_arrive, 1);
        while (atomicAdd(&g_bar_arrive, 0) < nb) { }
        int d = atomicAdd(&g_bar_depart, 1);
        if (d == nb - 1) {
            g_bar_arrive = 0;
            g_bar_depart = 0;
            __threadfence();
        }
    }
    __syncthreads();
}

// ---------------- launch 1: count + scan (fused, persistent) ---------------
__global__ void __launch_bounds__(1024) csr_scan_kernel(
        const int* __restrict__ dst, int e, int n, int nb) {
    for (int i = blockIdx.x * 1024 + threadIdx.x; i < e; i += nb * 1024)
        atomicAdd(&g_cnt[clampi(dst[i], 0, n - 1)], 1);

    grid_barrier(nb);

    __shared__ int sm[1024];
    __shared__ int prefix_sm;
    const int b = blockIdx.x;
    const int i = b * 1024 + threadIdx.x;

    int v = (i < n) ? g_cnt[i] : 0;
    sm[threadIdx.x] = v;
    __syncthreads();
    #pragma unroll
    for (int off = 1; off < 1024; off <<= 1) {
        int t = (threadIdx.x >= off) ? sm[threadIdx.x - off] : 0;
        __syncthreads();
        sm[threadIdx.x] += t;
        __syncthreads();
    }
    const int total = sm[1023];

    if (threadIdx.x == 0) {
        prefix_sm = 0;
        g_blocksum[b] = total;
        __threadfence();
        atomicExch(&g_flag[b], 1);
    }
    __syncthreads();

    int local = 0;
    for (int p = threadIdx.x; p < b; p += 1024) {
        while (atomicAdd(&g_flag[p], 0) == 0) { }
        local += g_blocksum[p];
    }
    if (local) atomicAdd(&prefix_sm, local);
    __syncthreads();
    const int prefix = prefix_sm;

    if (i < n) {
        int rs = prefix + sm[threadIdx.x] - v;
        g_rowstart[i] = rs;
        g_fillctr[i]  = rs;
        g_dinv[i]     = rsqrtf((float)v + 1.0f);
        g_cnt[i]      = 0;
    }
    if (b == nb - 1 && threadIdx.x == 0) g_rowstart[n] = prefix + total;
}

// ---------------- launch 2: fill edges (and reset lookback flags) ---------
__global__ void fill_kernel(const int* __restrict__ src,
                            const int* __restrict__ dst, int e, int n, int nb) {
    int i = blockIdx.x * blockDim.x + threadIdx.x;
    if (i < nb) g_flag[i] = 0;
    if (i >= e) return;
    int s = clampi(src[i], 0, n - 1);
    int d = clampi(dst[i], 0, n - 1);
    int pos = atomicAdd(&g_fillctr[d], 1);
    g_edge[pos] = make_int2(s, __float_as_int(g_dinv[s] * g_dinv[d]));
}

// ---------------- aggregate in x-space (64 ch) ----------------
__global__ void __launch_bounds__(256)
agg_kernel(const float* __restrict__ xin, int n) {
    int node = (blockIdx.x * blockDim.x + threadIdx.x) >> 5;
    if (node >= n) return;
    int lane = threadIdx.x & 31;
    int half = lane >> 4;
    int hl = lane & 15;

    const float4* x4 = reinterpret_cast<const float4*>(xin);
    float4 acc = make_float4(0.f, 0.f, 0.f, 0.f);

    int e0 = g_rowstart[node];
    int e1 = g_rowstart[node + 1];
    #pragma unroll 4
    for (int t = e0 + half; t < e1; t += 2) {
        int2 ed = __ldg(&g_edge[t]);
        float c = __int_as_float(ed.y);
        float4 v = __ldg(&x4[(size_t)ed.x * 16 + hl]);
        acc.x = fmaf(v.x, c, acc.x);
        acc.y = fmaf(v.y, c, acc.y);
        acc.z = fmaf(v.z, c, acc.z);
        acc.w = fmaf(v.w, c, acc.w);
    }
    __syncwarp();
    acc.x += __shfl_xor_sync(0xffffffffu, acc.x, 16);
    acc.y += __shfl_xor_sync(0xffffffffu, acc.y, 16);
    acc.z += __shfl_xor_sync(0xffffffffu, acc.z, 16);
    acc.w += __shfl_xor_sync(0xffffffffu, acc.w, 16);

    if (half == 0) {
        float dv = g_dinv[node], s2 = dv * dv;
        float4 xs = __ldg(&x4[(size_t)node * 16 + hl]);
        acc.x = fmaf(xs.x, s2, acc.x);
        acc.y = fmaf(xs.y, s2, acc.y);
        acc.z = fmaf(xs.z, s2, acc.z);
        acc.w = fmaf(xs.w, s2, acc.w);
        reinterpret_cast<float4*>(g_y)[(size_t)node * 16 + hl] = acc;
    }
}

// ---------------- tensor-core tf32 GEMM + bias + GLU + residual -----------
// 256 threads = 8 warps = 2 row-groups x 4 col-groups.
// Warp (rg, cg): rows 16*rg..+15, n-tiles {16cg, 16cg+8, 16cg+64, 16cg+72}
// (a-tile p pairs with g-tile p+2 => GLU is thread-local).
#define YS 68     // ysp row stride (bank-conflict-free A frags)
#define WS 136    // wsp row stride (bank-conflict-free B frags)
__global__ void __launch_bounds__(256)
gemm_glu_kernel(const float* __restrict__ xin, float* __restrict__ xout,
                const float* __restrict__ W, const float* __restrict__ b,
                int n) {
    __shared__ unsigned int wsp[C_IN * WS];   // 34.8 KB (tf32 bits)
    __shared__ unsigned int ysp[GRPB * YS];   //  8.7 KB (tf32 bits)

    const int t = threadIdx.x;
    const int warp = t >> 5;
    const int lane = t & 31;
    const int rg = warp & 1;           // 0..1
    const int cg = warp >> 1;          // 0..3
    const int row0 = blockIdx.x * GRPB;
    const int r0 = lane >> 2;          // 0..7
    const int c0 = lane & 3;           // 0..3

    // stage W -> tf32 (coalesced)
    #pragma unroll
    for (int idx = t; idx < C_IN * C_OUT; idx += 256) {
        int k = idx >> 7, c = idx & 127;
        wsp[k * WS + c] = tf32_rna(W[idx]);
    }
    // stage y rows -> tf32
    #pragma unroll
    for (int idx = t; idx < GRPB * C_IN; idx += 256) {
        int r = idx >> 6, k = idx & 63;
        int row = row0 + r;
        float v = (row < n) ? g_y[(size_t)row * C_IN + k] : 0.0f;
        ysp[r * YS + k] = tf32_rna(v);
    }
    __syncthreads();

    // A fragments for this warp's 16 rows, all 8 k-tiles
    const int R = 16 * rg;
    unsigned int a[8][4];
    #pragma unroll
    for (int kt = 0; kt < 8; kt++) {
        a[kt][0] = ysp[(R + r0) * YS + 8 * kt + c0];
        a[kt][1] = ysp[(R + r0 + 8) * YS + 8 * kt + c0];
        a[kt][2] = ysp[(R + r0) * YS + 8 * kt + c0 + 4];
        a[kt][3] = ysp[(R + r0 + 8) * YS + 8 * kt + c0 + 4];
    }

    const int nt[4] = {16 * cg, 16 * cg + 8, 16 * cg + 64, 16 * cg + 72};
    float d[4][4];
    #pragma unroll
    for (int p = 0; p < 4; p++)
        #pragma unroll
        for (int q = 0; q < 4; q++) d[p][q] = 0.0f;

    #pragma unroll
    for (int kt = 0; kt < 8; kt++) {
        #pragma unroll
        for (int p = 0; p < 4; p++) {
            unsigned int b0 = wsp[(8 * kt + c0) * WS + nt[p] + r0];
            unsigned int b1 = wsp[(8 * kt + c0 + 4) * WS + nt[p] + r0];
            mma_tf32(d[p][0], d[p][1], d[p][2], d[p][3],
                     a[kt][0], a[kt][1], a[kt][2], a[kt][3], b0, b1);
        }
    }

    // epilogue: bias + GLU + residual. a-tile p (cols nt[p]) + g-tile p+2.
    #pragma unroll
    for (int p = 0; p < 2; p++) {
        int col = nt[p] + 2 * c0;
        float ba0 = __ldg(&b[col]),      ba1 = __ldg(&b[col + 1]);
        float bg0 = __ldg(&b[col + 64]), bg1 = __ldg(&b[col + 65]);
        #pragma unroll
        for (int h = 0; h < 2; h++) {
            int row = row0 + R + r0 + 8 * h;
            if (row < n) {
                float av0 = d[p][2 * h + 0] + ba0;
                float av1 = d[p][2 * h + 1] + ba1;
                float gv0 = d[p + 2][2 * h + 0] + bg0;
                float gv1 = d[p + 2][2 * h + 1] + bg1;
                float2 res = *reinterpret_cast<const float2*>(
                    &xin[(size_t)row * C_IN + col]);
                float o0 = fmaf(av0, 1.0f / (1.0f + expf(-gv0)), res.x);
                float o1 = fmaf(av1, 1.0f / (1.0f + expf(-gv1)), res.y);
                *reinterpret_cast<float2*>(&xout[(size_t)row * C_IN + col]) =
                    make_float2(o0, o1);
            }
        }
    }
}

extern "C" void kernel_launch(void* const* d_in, const int* in_sizes, int n_in,
                              void* d_out, int out_size) {
    // Identify inputs by SIZE:
    //   x: == out_size (6.4M f32); edge_index: largest rest (3.2M i32);
    //   Ws: next (24576 f32); bs: smallest (384 f32)
    const float* x = nullptr; const float* Ws = nullptr; const float* bs = nullptr;
    const int* ei = nullptr;
    int ei_elems = 0, Ws_elems = 0;
    int used[16] = {0};
    for (int i = 0; i < n_in; i++)
        if (!x && in_sizes[i] == out_size) { x = (const float*)d_in[i]; used[i] = 1; break; }
    {
        int best = -1, bsz = -1;
        for (int i = 0; i < n_in; i++)
            if (!used[i] && in_sizes[i] > bsz) { bsz = in_sizes[i]; best = i; }
        ei = (const int*)d_in[best]; ei_elems = bsz; used[best] = 1;
    }
    {
        int best = -1, bsz = -1;
        for (int i = 0; i < n_in; i++)
            if (!used[i] && in_sizes[i] > bsz) { bsz = in_sizes[i]; best = i; }
        Ws = (const float*)d_in[best]; Ws_elems = bsz; used[best] = 1;
    }
    for (int i = 0; i < n_in; i++)
        if (!used[i]) { bs = (const float*)d_in[i]; used[i] = 1; break; }

    const int n = out_size / C_IN;
    const int e = ei_elems / 2;
    const int L = Ws_elems / (C_IN * C_OUT);
    const int* src = ei;
    const int* dst = ei + e;
    const int nb = (n + 1023) / 1024;   // 98 blocks, all resident

    float *x0, *x1;
    cudaGetSymbolAddress((void**)&x0, g_x0);
    cudaGetSymbolAddress((void**)&x1, g_x1);

    // ---- CSR build: 2 launches ----
    csr_scan_kernel<<<nb, 1024>>>(dst, e, n, nb);
    fill_kernel<<<(e + 255) / 256, 256>>>(src, dst, e, n, nb);

    // ---- layers (gemm of layer 0 is launch 4 -> profiled) ----
    const float* xin = x;
    for (int l = 0; l < L; l++) {
        float* xout = (l == L - 1) ? (float*)d_out : ((l & 1) ? x1 : x0);
        agg_kernel<<<(n * 32 + 255) / 256, 256>>>(xin, n);
        gemm_glu_kernel<<<(n + GRPB - 1) / GRPB, 256>>>(
            xin, xout, Ws + (size_t)l * C_IN * C_OUT, bs + (size_t)l * C_OUT, n);
        xin = xout;
    }
}

// round 17
// speedup vs baseline: 1.3330x; 1.0591x over previous
#include <cuda_runtime.h>
#include <math.h>

#define NMAX 100000
#define EMAX 1600000
#define C_IN 64
#define C_OUT 128
#define GRPB 64                      // gemm rows per block
#define YS 68                        // ysp row stride (uints)
#define WS 136                       // wsp row stride (uints)
#define GEMM_SMEM ((C_IN * WS + GRPB * YS) * 4)
#define NB_SCAN ((NMAX + 1023) / 1024)

// Scratch (device globals — no allocations allowed)
__device__ unsigned int g_y[(size_t)NMAX * C_IN];     // tf32 bits of y
__device__ unsigned int g_wt[3 * C_IN * C_OUT];       // tf32 bits of W (all layers)
__device__ float g_x0[(size_t)NMAX * C_IN];
__device__ float g_x1[(size_t)NMAX * C_IN];
__device__ float g_dinv[NMAX];
__device__ int   g_cnt[NMAX];        // must be 0 at entry of every call (invariant)
__device__ int   g_fillctr[NMAX];
__device__ int   g_rowstart[NMAX + 1];
__device__ int2  g_edge[EMAX];       // {srcid, coef bits}
__device__ int   g_blocksum[NB_SCAN];
__device__ int   g_flag[NB_SCAN];    // must be 0 at entry (reset by fill_kernel)
__device__ int   g_bar_arrive;
__device__ int   g_bar_depart;

__device__ __forceinline__ int clampi(int v, int lo, int hi) {
    return v < lo ? lo : (v > hi ? hi : v);
}

__device__ __forceinline__ unsigned int tf32_rna(float f) {
    unsigned int r;
    asm("cvt.rna.tf32.f32 %0, %1;" : "=r"(r) : "f"(f));
    return r;
}

__device__ __forceinline__ void mma_tf32(
    float& d0, float& d1, float& d2, float& d3,
    unsigned int a0, unsigned int a1, unsigned int a2, unsigned int a3,
    unsigned int b0, unsigned int b1) {
    asm("mma.sync.aligned.m16n8k8.row.col.f32.tf32.tf32.f32 "
        "{%0,%1,%2,%3}, {%4,%5,%6,%7}, {%8,%9}, {%0,%1,%2,%3};"
        : "+f"(d0), "+f"(d1), "+f"(d2), "+f"(d3)
        : "r"(a0), "r"(a1), "r"(a2), "r"(a3), "r"(b0), "r"(b1));
}

// self-resetting grid barrier (all nb blocks resident)
__device__ __forceinline__ void grid_barrier(int nb) {
    __syncthreads();
    if (threadIdx.x == 0) {
        __threadfence();
        atomicAdd(&g_bar_arrive, 1);
        while (atomicAdd(&g_bar_arrive, 0) < nb) { }
        int d = atomicAdd(&g_bar_depart, 1);
        if (d == nb - 1) {
            g_bar_arrive = 0;
            g_bar_depart = 0;
            __threadfence();
        }
    }
    __syncthreads();
}

// ---------------- launch 1: count + scan (fused, persistent) ---------------
__global__ void __launch_bounds__(1024) csr_scan_kernel(
        const int* __restrict__ dst, int e, int n, int nb) {
    for (int i = blockIdx.x * 1024 + threadIdx.x; i < e; i += nb * 1024)
        atomicAdd(&g_cnt[clampi(dst[i], 0, n - 1)], 1);

    grid_barrier(nb);

    __shared__ int sm[1024];
    __shared__ int prefix_sm;
    const int b = blockIdx.x;
    const int i = b * 1024 + threadIdx.x;

    int v = (i < n) ? g_cnt[i] : 0;
    sm[threadIdx.x] = v;
    __syncthreads();
    #pragma unroll
    for (int off = 1; off < 1024; off <<= 1) {
        int t = (threadIdx.x >= off) ? sm[threadIdx.x - off] : 0;
        __syncthreads();
        sm[threadIdx.x] += t;
        __syncthreads();
    }
    const int total = sm[1023];

    if (threadIdx.x == 0) {
        prefix_sm = 0;
        g_blocksum[b] = total;
        __threadfence();
        atomicExch(&g_flag[b], 1);
    }
    __syncthreads();

    int local = 0;
    for (int p = threadIdx.x; p < b; p += 1024) {
        while (atomicAdd(&g_flag[p], 0) == 0) { }
        local += g_blocksum[p];
    }
    if (local) atomicAdd(&prefix_sm, local);
    __syncthreads();
    const int prefix = prefix_sm;

    if (i < n) {
        int rs = prefix + sm[threadIdx.x] - v;
        g_rowstart[i] = rs;
        g_fillctr[i]  = rs;
        g_dinv[i]     = rsqrtf((float)v + 1.0f);
        g_cnt[i]      = 0;
    }
    if (b == nb - 1 && threadIdx.x == 0) g_rowstart[n] = prefix + total;
}

// ---------------- launch 2: fill edges + reset flags + convert W ----------
__global__ void fill_kernel(const int* __restrict__ src,
                            const int* __restrict__ dst,
                            const float* __restrict__ Ws, int wtotal,
                            int e, int n, int nb) {
    int i = blockIdx.x * blockDim.x + threadIdx.x;
    if (i < nb) g_flag[i] = 0;
    if (i < wtotal) g_wt[i] = tf32_rna(Ws[i]);    // one-time W -> tf32
    if (i >= e) return;
    int s = clampi(src[i], 0, n - 1);
    int d = clampi(dst[i], 0, n - 1);
    int pos = atomicAdd(&g_fillctr[d], 1);
    g_edge[pos] = make_int2(s, __float_as_int(g_dinv[s] * g_dinv[d]));
}

// ---------------- aggregate in x-space (64 ch) -> tf32 bits ---------------
__global__ void __launch_bounds__(256)
agg_kernel(const float* __restrict__ xin, int n) {
    int node = (blockIdx.x * blockDim.x + threadIdx.x) >> 5;
    if (node >= n) return;
    int lane = threadIdx.x & 31;
    int half = lane >> 4;
    int hl = lane & 15;

    const float4* x4 = reinterpret_cast<const float4*>(xin);
    float4 acc = make_float4(0.f, 0.f, 0.f, 0.f);

    int e0 = g_rowstart[node];
    int e1 = g_rowstart[node + 1];
    #pragma unroll 4
    for (int t = e0 + half; t < e1; t += 2) {
        int2 ed = __ldg(&g_edge[t]);
        float c = __int_as_float(ed.y);
        float4 v = __ldg(&x4[(size_t)ed.x * 16 + hl]);
        acc.x = fmaf(v.x, c, acc.x);
        acc.y = fmaf(v.y, c, acc.y);
        acc.z = fmaf(v.z, c, acc.z);
        acc.w = fmaf(v.w, c, acc.w);
    }
    __syncwarp();
    acc.x += __shfl_xor_sync(0xffffffffu, acc.x, 16);
    acc.y += __shfl_xor_sync(0xffffffffu, acc.y, 16);
    acc.z += __shfl_xor_sync(0xffffffffu, acc.z, 16);
    acc.w += __shfl_xor_sync(0xffffffffu, acc.w, 16);

    if (half == 0) {
        float dv = g_dinv[node], s2 = dv * dv;
        float4 xs = __ldg(&x4[(size_t)node * 16 + hl]);
        uint4 o;
        o.x = tf32_rna(fmaf(xs.x, s2, acc.x));
        o.y = tf32_rna(fmaf(xs.y, s2, acc.y));
        o.z = tf32_rna(fmaf(xs.z, s2, acc.z));
        o.w = tf32_rna(fmaf(xs.w, s2, acc.w));
        reinterpret_cast<uint4*>(g_y)[(size_t)node * 16 + hl] = o;
    }
}

// ---------------- tensor-core tf32 GEMM + bias + GLU + residual -----------
// 256 threads = 8 warps = 4 row-groups x 2 col-groups. GRPB=64 rows.
// Warp (rg, cg): rows 16*rg..+15; a-tiles {32cg+8p} p=0..3, g-tiles +64
// (GLU pair thread-local).
__global__ void __launch_bounds__(256)
gemm_glu_kernel(const float* __restrict__ xin, float* __restrict__ xout,
                const unsigned int* __restrict__ wt,
                const float* __restrict__ b, int n) {
    extern __shared__ unsigned int smem_u[];
    unsigned int* wsp = smem_u;                 // C_IN * WS
    unsigned int* ysp = smem_u + C_IN * WS;     // GRPB * YS

    const int t = threadIdx.x;
    const int warp = t >> 5;
    const int lane = t & 31;
    const int rg = warp >> 1;          // 0..3
    const int cg = warp & 1;           // 0..1
    const int row0 = blockIdx.x * GRPB;
    const int r0 = lane >> 2;          // 0..7
    const int c0 = lane & 3;           // 0..3
    const int R = 16 * rg;

    // stage W bits (pure copy, coalesced)
    #pragma unroll
    for (int idx = t; idx < C_IN * C_OUT; idx += 256)
        wsp[(idx >> 7) * WS + (idx & 127)] = wt[idx];

    // stage y bits (uint4)
    {
        const uint4* ysrc = reinterpret_cast<const uint4*>(g_y);
        #pragma unroll
        for (int idx = t; idx < GRPB * (C_IN / 4); idx += 256) {
            int r = idx >> 4, k4 = idx & 15;
            int row = row0 + r;
            uint4 v = (row < n) ? ysrc[(size_t)row * 16 + k4]
                                : make_uint4(0u, 0u, 0u, 0u);
            *reinterpret_cast<uint4*>(&ysp[r * YS + 4 * k4]) = v;
        }
    }
    __syncthreads();

    float d[8][4];
    #pragma unroll
    for (int p = 0; p < 8; p++)
        #pragma unroll
        for (int q = 0; q < 4; q++) d[p][q] = 0.0f;

    #pragma unroll
    for (int kt = 0; kt < 8; kt++) {
        unsigned int a0 = ysp[(R + r0) * YS + 8 * kt + c0];
        unsigned int a1 = ysp[(R + r0 + 8) * YS + 8 * kt + c0];
        unsigned int a2 = ysp[(R + r0) * YS + 8 * kt + c0 + 4];
        unsigned int a3 = ysp[(R + r0 + 8) * YS + 8 * kt + c0 + 4];
        #pragma unroll
        for (int p = 0; p < 8; p++) {
            int nt = 32 * cg + 8 * (p & 3) + 64 * (p >> 2);
            unsigned int b0 = wsp[(8 * kt + c0) * WS + nt + r0];
            unsigned int b1 = wsp[(8 * kt + c0 + 4) * WS + nt + r0];
            mma_tf32(d[p][0], d[p][1], d[p][2], d[p][3], a0, a1, a2, a3, b0, b1);
        }
    }

    // epilogue: bias + GLU + residual. a-tile p pairs g-tile p+4.
    #pragma unroll
    for (int p = 0; p < 4; p++) {
        int col = 32 * cg + 8 * p + 2 * c0;
        float ba0 = __ldg(&b[col]),      ba1 = __ldg(&b[col + 1]);
        float bg0 = __ldg(&b[col + 64]), bg1 = __ldg(&b[col + 65]);
        #pragma unroll
        for (int h = 0; h < 2; h++) {
            int row = row0 + R + r0 + 8 * h;
            if (row < n) {
                float av0 = d[p][2 * h + 0] + ba0;
                float av1 = d[p][2 * h + 1] + ba1;
                float gv0 = d[p + 4][2 * h + 0] + bg0;
                float gv1 = d[p + 4][2 * h + 1] + bg1;
                float2 res = *reinterpret_cast<const float2*>(
                    &xin[(size_t)row * C_IN + col]);
                float o0 = fmaf(av0, 1.0f / (1.0f + expf(-gv0)), res.x);
                float o1 = fmaf(av1, 1.0f / (1.0f + expf(-gv1)), res.y);
                *reinterpret_cast<float2*>(&xout[(size_t)row * C_IN + col]) =
                    make_float2(o0, o1);
            }
        }
    }
}

extern "C" void kernel_launch(void* const* d_in, const int* in_sizes, int n_in,
                              void* d_out, int out_size) {
    // Identify inputs by SIZE:
    //   x: == out_size (6.4M f32); edge_index: largest rest (3.2M i32);
    //   Ws: next (24576 f32); bs: smallest (384 f32)
    const float* x = nullptr; const float* Ws = nullptr; const float* bs = nullptr;
    const int* ei = nullptr;
    int ei_elems = 0, Ws_elems = 0;
    int used[16] = {0};
    for (int i = 0; i < n_in; i++)
        if (!x && in_sizes[i] == out_size) { x = (const float*)d_in[i]; used[i] = 1; break; }
    {
        int best = -1, bsz = -1;
        for (int i = 0; i < n_in; i++)
            if (!used[i] && in_sizes[i] > bsz) { bsz = in_sizes[i]; best = i; }
        ei = (const int*)d_in[best]; ei_elems = bsz; used[best] = 1;
    }
    {
        int best = -1, bsz = -1;
        for (int i = 0; i < n_in; i++)
            if (!used[i] && in_sizes[i] > bsz) { bsz = in_sizes[i]; best = i; }
        Ws = (const float*)d_in[best]; Ws_elems = bsz; used[best] = 1;
    }
    for (int i = 0; i < n_in; i++)
        if (!used[i]) { bs = (const float*)d_in[i]; used[i] = 1; break; }

    const int n = out_size / C_IN;
    const int e = ei_elems / 2;
    const int L = Ws_elems / (C_IN * C_OUT);
    const int* src = ei;
    const int* dst = ei + e;
    const int nb = (n + 1023) / 1024;   // 98 blocks, all resident

    float *x0, *x1;
    cudaGetSymbolAddress((void**)&x0, g_x0);
    cudaGetSymbolAddress((void**)&x1, g_x1);
    unsigned int* wt;
    cudaGetSymbolAddress((void**)&wt, g_wt);

    static int smem_set = 0;
    if (!smem_set) {
        cudaFuncSetAttribute(gemm_glu_kernel,
                             cudaFuncAttributeMaxDynamicSharedMemorySize,
                             GEMM_SMEM);
        smem_set = 1;
    }

    // ---- CSR build + W convert: 2 launches ----
    csr_scan_kernel<<<nb, 1024>>>(dst, e, n, nb);
    fill_kernel<<<(e + 255) / 256, 256>>>(src, dst, Ws, Ws_elems, e, n, nb);

    // ---- layers (gemm of layer 0 is launch 4 -> profiled) ----
    const float* xin = x;
    for (int l = 0; l < L; l++) {
        float* xout = (l == L - 1) ? (float*)d_out : ((l & 1) ? x1 : x0);
        agg_kernel<<<(n * 32 + 255) / 256, 256>>>(xin, n);
        gemm_glu_kernel<<<(n + GRPB - 1) / GRPB, 256, GEMM_SMEM>>>(
            xin, xout, wt + (size_t)l * C_IN * C_OUT, bs + (size_t)l * C_OUT, n);
        xin = xout;
    }
}